// round 1
// baseline (speedup 1.0000x reference)
#include <cuda_runtime.h>
#include <math.h>

#define B 32
#define S 64
#define T 64
#define E 512
#define H 512
#define V 32000
#define G3 1536   // 3*H

// ---------------- scratch (static device allocations; allowed) ----------------
__device__ float g_esrc[B * S * E];          // 4 MB
__device__ float g_etgt[B * T * E];          // 4 MB
__device__ float g_gxf[B * S * G3];          // 12 MB
__device__ float g_gxb[B * S * G3];          // 12 MB
__device__ float g_gxemb[B * T * G3];        // 12 MB
__device__ float g_srchid[B * S * 2 * H];    // 8 MB  [b,s, 2H] (fwd half | bwd half)
__device__ float g_Uh[B * S * H];            // 4 MB
__device__ float g_hTf[2][H * B];            // enc fwd hidden, transposed [k][b], ping-pong
__device__ float g_hTb[2][H * B];            // enc bwd
__device__ float g_hTd[2][H * B];            // dec
__device__ float g_ghd[G3 * B];              // dec gh, transposed [j][b]
__device__ float g_Ah[B * H];                // [b][k]
__device__ float g_cT[2 * H * B];            // context transposed [k][b]
__device__ float g_decout[B * T * H];        // 4 MB
__device__ float g_logits[(size_t)B * T * V];// 262 MB
__device__ float g_rowres[B * T];

__device__ __forceinline__ float sigm(float x) { return 1.0f / (1.0f + expf(-x)); }

// ---------------- init: zero hidden states ----------------
__global__ void zero_h_kernel() {
    int idx = blockIdx.x * blockDim.x + threadIdx.x;
    if (idx < H * B) {
        g_hTf[0][idx] = 0.f; g_hTf[1][idx] = 0.f;
        g_hTb[0][idx] = 0.f; g_hTb[1][idx] = 0.f;
        g_hTd[0][idx] = 0.f; g_hTd[1][idx] = 0.f;
    }
}

// ---------------- embedding gather ----------------
__global__ __launch_bounds__(128) void embed_kernel(
    const int* __restrict__ src_seqs, const int* __restrict__ tgt_seqs,
    const float* __restrict__ src_emb, const float* __restrict__ tgt_emb)
{
    int blk = blockIdx.x;
    int tid = threadIdx.x;   // 128 threads, each one float4 of 512-float row
    if (blk < B * S) {
        int tok = src_seqs[blk];
        const float4* s = (const float4*)(src_emb + (size_t)tok * E);
        float4* d = (float4*)(g_esrc + (size_t)blk * E);
        d[tid] = s[tid];
    } else {
        int r = blk - B * S;
        int tok = tgt_seqs[r];
        const float4* s = (const float4*)(tgt_emb + (size_t)tok * E);
        float4* d = (float4*)(g_etgt + (size_t)r * E);
        d[tid] = s[tid];
    }
}

// ---------------- generic fp32 GEMM: C[M,N] = A[M,K] @ W[N,K]^T + bias ----------------
#define GBM 128
#define GBN 64
#define GBK 16
__global__ __launch_bounds__(256) void gemm_nt(
    const float* __restrict__ A, int lda,
    const float* __restrict__ W, int ldw,
    const float* __restrict__ bias,
    float* __restrict__ C, int ldc, int K)
{
    __shared__ float As[GBK][GBM];
    __shared__ float Bs[GBK][GBN];
    int tid = threadIdx.x;
    int m0 = blockIdx.y * GBM;
    int n0 = blockIdx.x * GBN;
    int tx = tid & 15, ty = tid >> 4;

    float acc[8][4];
#pragma unroll
    for (int i = 0; i < 8; i++)
#pragma unroll
        for (int j = 0; j < 4; j++) acc[i][j] = 0.f;

    int ar0 = tid >> 2;             // 0..63 (+64 for second)
    int ak0 = (tid & 3) * 4;
    int bn = tid >> 2;              // 0..63
    int bk0 = (tid & 3) * 4;

    for (int k0 = 0; k0 < K; k0 += GBK) {
#pragma unroll
        for (int h = 0; h < 2; h++) {
            int r = ar0 + h * 64;
            float4 v = *(const float4*)(A + (size_t)(m0 + r) * lda + k0 + ak0);
            As[ak0 + 0][r] = v.x; As[ak0 + 1][r] = v.y;
            As[ak0 + 2][r] = v.z; As[ak0 + 3][r] = v.w;
        }
        {
            float4 v = *(const float4*)(W + (size_t)(n0 + bn) * ldw + k0 + bk0);
            Bs[bk0 + 0][bn] = v.x; Bs[bk0 + 1][bn] = v.y;
            Bs[bk0 + 2][bn] = v.z; Bs[bk0 + 3][bn] = v.w;
        }
        __syncthreads();
#pragma unroll
        for (int kk = 0; kk < GBK; kk++) {
            float a[8], b[4];
#pragma unroll
            for (int i = 0; i < 8; i++) a[i] = As[kk][ty * 8 + i];
#pragma unroll
            for (int j = 0; j < 4; j++) b[j] = Bs[kk][tx * 4 + j];
#pragma unroll
            for (int i = 0; i < 8; i++)
#pragma unroll
                for (int j = 0; j < 4; j++) acc[i][j] = fmaf(a[i], b[j], acc[i][j]);
        }
        __syncthreads();
    }
    float b4[4];
#pragma unroll
    for (int j = 0; j < 4; j++) b4[j] = bias[n0 + tx * 4 + j];
#pragma unroll
    for (int i = 0; i < 8; i++) {
        int m = m0 + ty * 8 + i;
        float4 o;
        o.x = acc[i][0] + b4[0]; o.y = acc[i][1] + b4[1];
        o.z = acc[i][2] + b4[2]; o.w = acc[i][3] + b4[3];
        *(float4*)(C + (size_t)m * ldc + n0 + tx * 4) = o;
    }
}

// ---------------- encoder step (both directions fused; 128 CTAs x 128 thr) ----------------
__global__ __launch_bounds__(128) void enc_step(
    int i,
    const float* __restrict__ Whh_f, const float* __restrict__ bhh_f,
    const float* __restrict__ Whh_b, const float* __restrict__ bhh_b,
    const int* __restrict__ src_lengths)
{
    int lane = threadIdx.x & 31;           // = b
    int w = threadIdx.x >> 5;              // 0..3
    int bx = blockIdx.x;                   // 0..127
    int dir = bx >> 6;
    int j0 = (bx & 63) * 8 + w * 2;        // this thread: j0, j0+1
    int t = dir ? (S - 1 - i) : i;
    int pin = i & 1, pout = pin ^ 1;
    const float* hTin = dir ? g_hTb[pin] : g_hTf[pin];
    float* hTout = dir ? g_hTb[pout] : g_hTf[pout];
    const float* gx = dir ? g_gxb : g_gxf;
    const float* Whh = dir ? Whh_b : Whh_f;
    const float* bhh = dir ? bhh_b : bhh_f;

    float ar0 = bhh[j0],         az0 = bhh[H + j0],     an0 = bhh[2 * H + j0];
    float ar1 = bhh[j0 + 1],     az1 = bhh[H + j0 + 1], an1 = bhh[2 * H + j0 + 1];

    const float* wr = Whh + (size_t)j0 * H;
    const float* wz = Whh + (size_t)(H + j0) * H;
    const float* wn = Whh + (size_t)(2 * H + j0) * H;

#pragma unroll 4
    for (int k = 0; k < H; k += 4) {
        float h0 = hTin[(k + 0) * B + lane];
        float h1 = hTin[(k + 1) * B + lane];
        float h2 = hTin[(k + 2) * B + lane];
        float h3 = hTin[(k + 3) * B + lane];
        float4 r0 = *(const float4*)(wr + k);
        float4 r1 = *(const float4*)(wr + H + k);
        float4 z0 = *(const float4*)(wz + k);
        float4 z1 = *(const float4*)(wz + H + k);
        float4 n0 = *(const float4*)(wn + k);
        float4 n1 = *(const float4*)(wn + H + k);
        ar0 = fmaf(r0.x, h0, ar0); ar0 = fmaf(r0.y, h1, ar0); ar0 = fmaf(r0.z, h2, ar0); ar0 = fmaf(r0.w, h3, ar0);
        ar1 = fmaf(r1.x, h0, ar1); ar1 = fmaf(r1.y, h1, ar1); ar1 = fmaf(r1.z, h2, ar1); ar1 = fmaf(r1.w, h3, ar1);
        az0 = fmaf(z0.x, h0, az0); az0 = fmaf(z0.y, h1, az0); az0 = fmaf(z0.z, h2, az0); az0 = fmaf(z0.w, h3, az0);
        az1 = fmaf(z1.x, h0, az1); az1 = fmaf(z1.y, h1, az1); az1 = fmaf(z1.z, h2, az1); az1 = fmaf(z1.w, h3, az1);
        an0 = fmaf(n0.x, h0, an0); an0 = fmaf(n0.y, h1, an0); an0 = fmaf(n0.z, h2, an0); an0 = fmaf(n0.w, h3, an0);
        an1 = fmaf(n1.x, h0, an1); an1 = fmaf(n1.y, h1, an1); an1 = fmaf(n1.z, h2, an1); an1 = fmaf(n1.w, h3, an1);
    }

    int base = (lane * S + t) * G3;
    int mask = t < src_lengths[lane];

    // j0
    {
        float r = sigm(gx[base + j0] + ar0);
        float z = sigm(gx[base + H + j0] + az0);
        float n = tanhf(gx[base + 2 * H + j0] + r * an0);
        float hprev = hTin[j0 * B + lane];
        float hnew = (1.f - z) * n + z * hprev;
        hTout[j0 * B + lane] = mask ? hnew : hprev;
        g_srchid[(size_t)(lane * S + t) * (2 * H) + dir * H + j0] = mask ? hnew : 0.f;
    }
    // j0+1
    {
        int j1 = j0 + 1;
        float r = sigm(gx[base + j1] + ar1);
        float z = sigm(gx[base + H + j1] + az1);
        float n = tanhf(gx[base + 2 * H + j1] + r * an1);
        float hprev = hTin[j1 * B + lane];
        float hnew = (1.f - z) * n + z * hprev;
        hTout[j1 * B + lane] = mask ? hnew : hprev;
        g_srchid[(size_t)(lane * S + t) * (2 * H) + dir * H + j1] = mask ? hnew : 0.f;
    }
}

// ---------------- decoder stage 1: gh = h@Whh^T + bhh  and  Ah = h@A_W^T + A_b ----------------
__global__ __launch_bounds__(128) void dec_d1(
    int i,
    const float* __restrict__ dec_Whh, const float* __restrict__ dec_bhh,
    const float* __restrict__ A_W, const float* __restrict__ A_b)
{
    int lane = threadIdx.x & 31, w = threadIdx.x >> 5;
    int j0 = blockIdx.x * 16 + w * 4;       // grid 128 covers j in [0,2048)
    const float* hTin = g_hTd[i & 1];
    bool is_att = (j0 >= G3);

    const float* wp[4];
    float acc[4];
#pragma unroll
    for (int jj = 0; jj < 4; jj++) {
        int j = j0 + jj;
        if (!is_att) { wp[jj] = dec_Whh + (size_t)j * H; acc[jj] = dec_bhh[j]; }
        else { int ja = j - G3; wp[jj] = A_W + (size_t)ja * H; acc[jj] = A_b[ja]; }
    }
#pragma unroll 4
    for (int k = 0; k < H; k += 4) {
        float h0 = hTin[(k + 0) * B + lane];
        float h1 = hTin[(k + 1) * B + lane];
        float h2 = hTin[(k + 2) * B + lane];
        float h3 = hTin[(k + 3) * B + lane];
#pragma unroll
        for (int jj = 0; jj < 4; jj++) {
            float4 wv = *(const float4*)(wp[jj] + k);
            acc[jj] = fmaf(wv.x, h0, acc[jj]);
            acc[jj] = fmaf(wv.y, h1, acc[jj]);
            acc[jj] = fmaf(wv.z, h2, acc[jj]);
            acc[jj] = fmaf(wv.w, h3, acc[jj]);
        }
    }
#pragma unroll
    for (int jj = 0; jj < 4; jj++) {
        int j = j0 + jj;
        if (!is_att) g_ghd[j * B + lane] = acc[jj];
        else g_Ah[lane * H + (j - G3)] = acc[jj];
    }
}

// ---------------- decoder stage 2: attention scores + softmax + context ----------------
__global__ __launch_bounds__(256) void dec_d2(
    const float* __restrict__ A_v, const int* __restrict__ src_lengths)
{
    __shared__ float sAh[H];
    __shared__ float se[S];
    int b = blockIdx.x, tid = threadIdx.x;
    int lane = tid & 31, w = tid >> 5;   // 8 warps
    sAh[tid] = g_Ah[b * H + tid];
    sAh[tid + 256] = g_Ah[b * H + tid + 256];
    __syncthreads();

    int len = src_lengths[b];
#pragma unroll
    for (int si = 0; si < 8; si++) {
        int s = w * 8 + si;
        const float* uh = g_Uh + (size_t)(b * S + s) * H;
        float p = 0.f;
        for (int k = lane; k < H; k += 32)
            p += A_v[k] * tanhf(uh[k] + sAh[k]);
#pragma unroll
        for (int off = 16; off; off >>= 1) p += __shfl_xor_sync(0xffffffffu, p, off);
        if (lane == 0) se[s] = (s < len) ? p : -1e9f;
    }
    __syncthreads();

    if (w == 0) {   // softmax over 64 in one warp
        float e0 = se[lane], e1 = se[lane + 32];
        float m = fmaxf(e0, e1);
#pragma unroll
        for (int off = 16; off; off >>= 1) m = fmaxf(m, __shfl_xor_sync(0xffffffffu, m, off));
        float x0 = expf(e0 - m), x1 = expf(e1 - m);
        float sm = x0 + x1;
#pragma unroll
        for (int off = 16; off; off >>= 1) sm += __shfl_xor_sync(0xffffffffu, sm, off);
        se[lane] = x0 / sm;
        se[lane + 32] = x1 / sm;
    }
    __syncthreads();

    for (int k2 = tid; k2 < 2 * H; k2 += 256) {
        const float* sh = g_srchid + (size_t)(b * S) * (2 * H) + k2;
        float acc = 0.f;
#pragma unroll 8
        for (int s = 0; s < S; s++) acc = fmaf(se[s], sh[(size_t)s * (2 * H)], acc);
        g_cT[k2 * B + b] = acc;
    }
}

// ---------------- decoder stage 3: gx_c = c@Wih_c^T, gates, h update ----------------
__global__ __launch_bounds__(128) void dec_d3(
    int i, const float* __restrict__ dec_Wih, const int* __restrict__ tgt_lengths)
{
    int lane = threadIdx.x & 31, w = threadIdx.x >> 5;
    int jh = blockIdx.x * 4 + w;            // grid 128 covers jh in [0,512)
    int pin = i & 1, pout = pin ^ 1;

    float ar = 0.f, az = 0.f, an = 0.f;
    const float* wr = dec_Wih + (size_t)jh * G3 + 512;
    const float* wz = dec_Wih + (size_t)(512 + jh) * G3 + 512;
    const float* wn = dec_Wih + (size_t)(1024 + jh) * G3 + 512;

#pragma unroll 4
    for (int k = 0; k < 2 * H; k += 4) {
        float c0 = g_cT[(k + 0) * B + lane];
        float c1 = g_cT[(k + 1) * B + lane];
        float c2 = g_cT[(k + 2) * B + lane];
        float c3 = g_cT[(k + 3) * B + lane];
        float4 r4 = *(const float4*)(wr + k);
        float4 z4 = *(const float4*)(wz + k);
        float4 n4 = *(const float4*)(wn + k);
        ar = fmaf(r4.x, c0, ar); ar = fmaf(r4.y, c1, ar); ar = fmaf(r4.z, c2, ar); ar = fmaf(r4.w, c3, ar);
        az = fmaf(z4.x, c0, az); az = fmaf(z4.y, c1, az); az = fmaf(z4.z, c2, az); az = fmaf(z4.w, c3, az);
        an = fmaf(n4.x, c0, an); an = fmaf(n4.y, c1, an); an = fmaf(n4.z, c2, an); an = fmaf(n4.w, c3, an);
    }

    int base = (lane * T + i) * G3;
    float gxr = g_gxemb[base + jh] + ar;
    float gxz = g_gxemb[base + 512 + jh] + az;
    float gxn = g_gxemb[base + 1024 + jh] + an;
    float ghr = g_ghd[jh * B + lane];
    float ghz = g_ghd[(512 + jh) * B + lane];
    float ghn = g_ghd[(1024 + jh) * B + lane];
    float r = sigm(gxr + ghr);
    float z = sigm(gxz + ghz);
    float n = tanhf(gxn + r * ghn);
    float hprev = g_hTd[pin][jh * B + lane];
    float hnew = (1.f - z) * n + z * hprev;
    int mask = i < tgt_lengths[lane];
    g_hTd[pout][jh * B + lane] = mask ? hnew : hprev;
    g_decout[(size_t)(lane * T + i) * H + jh] = mask ? hnew : 0.f;
}

// ---------------- per-row logsumexp + picked logprob ----------------
__global__ __launch_bounds__(256) void row_lse(const int* __restrict__ tgt_seqs)
{
    int row = blockIdx.x;           // b*T + t
    int b = row / T, t = row % T;
    const float* lg = g_logits + (size_t)row * V;
    __shared__ float sred[256];
    int tid = threadIdx.x;

    float m = -1e30f;
    for (int v = tid; v < V; v += 256) m = fmaxf(m, lg[v]);
    sred[tid] = m; __syncthreads();
    for (int s2 = 128; s2; s2 >>= 1) {
        if (tid < s2) sred[tid] = fmaxf(sred[tid], sred[tid + s2]);
        __syncthreads();
    }
    m = sred[0]; __syncthreads();

    float ss = 0.f;
    for (int v = tid; v < V; v += 256) ss += expf(lg[v] - m);
    sred[tid] = ss; __syncthreads();
    for (int s2 = 128; s2; s2 >>= 1) {
        if (tid < s2) sred[tid] += sred[tid + s2];
        __syncthreads();
    }
    if (tid == 0) {
        int goal = (t < T - 1) ? tgt_seqs[b * T + t + 1] : 0;
        float lse = m + logf(sred[0]);
        g_rowres[row] = (goal != 0) ? (lg[goal] - lse) : 0.f;
    }
}

// ---------------- final deterministic reduction ----------------
__global__ __launch_bounds__(256) void final_loss(
    const int* __restrict__ tgt_seqs, float* __restrict__ out)
{
    __shared__ float sp[256];
    __shared__ float sc[256];
    int tid = threadIdx.x;
    float ps = 0.f, pc = 0.f;
    for (int r = tid; r < B * T; r += 256) {
        ps += g_rowres[r];
        int b = r / T, t = r % T;
        int goal = (t < T - 1) ? tgt_seqs[b * T + t + 1] : 0;
        pc += (goal != 0) ? 1.f : 0.f;
    }
    sp[tid] = ps; sc[tid] = pc; __syncthreads();
    for (int s2 = 128; s2; s2 >>= 1) {
        if (tid < s2) { sp[tid] += sp[tid + s2]; sc[tid] += sc[tid + s2]; }
        __syncthreads();
    }
    if (tid == 0) out[0] = -sp[0] / sc[0];
}

// ---------------- host ----------------
extern "C" void kernel_launch(void* const* d_in, const int* in_sizes, int n_in,
                              void* d_out, int out_size)
{
    const int* src_seqs    = (const int*)d_in[0];
    const int* src_lengths = (const int*)d_in[1];
    const int* tgt_seqs    = (const int*)d_in[2];
    const int* tgt_lengths = (const int*)d_in[3];
    const float* src_emb   = (const float*)d_in[4];
    const float* enc_Wih_f = (const float*)d_in[5];
    const float* enc_Whh_f = (const float*)d_in[6];
    const float* enc_bih_f = (const float*)d_in[7];
    const float* enc_bhh_f = (const float*)d_in[8];
    const float* enc_Wih_b = (const float*)d_in[9];
    const float* enc_Whh_b = (const float*)d_in[10];
    const float* enc_bih_b = (const float*)d_in[11];
    const float* enc_bhh_b = (const float*)d_in[12];
    const float* tgt_emb   = (const float*)d_in[13];
    const float* dec_Wih   = (const float*)d_in[14];
    const float* dec_Whh   = (const float*)d_in[15];
    const float* dec_bih   = (const float*)d_in[16];
    const float* dec_bhh   = (const float*)d_in[17];
    const float* U_w       = (const float*)d_in[18];
    const float* U_b       = (const float*)d_in[19];
    const float* A_W       = (const float*)d_in[20];
    const float* A_b       = (const float*)d_in[21];
    const float* A_v       = (const float*)d_in[22];
    const float* out_w     = (const float*)d_in[23];
    const float* out_b     = (const float*)d_in[24];

    void *p_esrc, *p_etgt, *p_gxf, *p_gxb, *p_gxemb, *p_srchid, *p_Uh, *p_decout, *p_logits;
    cudaGetSymbolAddress(&p_esrc, g_esrc);
    cudaGetSymbolAddress(&p_etgt, g_etgt);
    cudaGetSymbolAddress(&p_gxf, g_gxf);
    cudaGetSymbolAddress(&p_gxb, g_gxb);
    cudaGetSymbolAddress(&p_gxemb, g_gxemb);
    cudaGetSymbolAddress(&p_srchid, g_srchid);
    cudaGetSymbolAddress(&p_Uh, g_Uh);
    cudaGetSymbolAddress(&p_decout, g_decout);
    cudaGetSymbolAddress(&p_logits, g_logits);

    zero_h_kernel<<<(H * B + 255) / 256, 256>>>();
    embed_kernel<<<B * S + B * T, 128>>>(src_seqs, tgt_seqs, src_emb, tgt_emb);

    // gx precompute GEMMs
    gemm_nt<<<dim3(G3 / GBN, (B * S) / GBM), 256>>>(
        (const float*)p_esrc, E, enc_Wih_f, E, enc_bih_f, (float*)p_gxf, G3, E);
    gemm_nt<<<dim3(G3 / GBN, (B * S) / GBM), 256>>>(
        (const float*)p_esrc, E, enc_Wih_b, E, enc_bih_b, (float*)p_gxb, G3, E);
    gemm_nt<<<dim3(G3 / GBN, (B * T) / GBM), 256>>>(
        (const float*)p_etgt, E, dec_Wih, G3, dec_bih, (float*)p_gxemb, G3, E);

    // encoder recurrence (fwd + bwd fused per step)
    for (int i = 0; i < S; i++)
        enc_step<<<128, 128>>>(i, enc_Whh_f, enc_bhh_f, enc_Whh_b, enc_bhh_b, src_lengths);

    // Uh = src_hidden @ U_w^T + U_b
    gemm_nt<<<dim3(H / GBN, (B * S) / GBM), 256>>>(
        (const float*)p_srchid, 2 * H, U_w, 2 * H, U_b, (float*)p_Uh, H, 2 * H);

    // decoder
    for (int i = 0; i < T; i++) {
        dec_d1<<<128, 128>>>(i, dec_Whh, dec_bhh, A_W, A_b);
        dec_d2<<<B, 256>>>(A_v, src_lengths);
        dec_d3<<<128, 128>>>(i, dec_Wih, tgt_lengths);
    }

    // logits = dec_out @ out_w^T + out_b
    gemm_nt<<<dim3(V / GBN, (B * T) / GBM), 256>>>(
        (const float*)p_decout, H, out_w, H, out_b, (float*)p_logits, V, H);

    row_lse<<<B * T, 256>>>(tgt_seqs);
    final_loss<<<1, 256>>>(tgt_seqs, (float*)d_out);
}

// round 2
// speedup vs baseline: 1.2663x; 1.2663x over previous
#include <cuda_runtime.h>
#include <math.h>

#define B 32
#define S 64
#define T 64
#define E 512
#define H 512
#define V 32000
#define G3 1536   // 3*H

#define ENC_BLOCKS 128
#define DEC_BLOCKS 128

// ---------------- scratch (static device allocations; allowed) ----------------
__device__ float g_esrc[B * S * E];
__device__ float g_etgt[B * T * E];
__device__ float g_gxf[B * S * G3];
__device__ float g_gxb[B * S * G3];
__device__ float g_gxemb[B * T * G3];
__device__ float g_srchid[B * S * 2 * H];    // [b,s,2H]
__device__ float g_Uh[B * S * H];
__device__ float g_hTf[2][H * B];            // packed float4 layout: idx=(k4*B+b)*4+c
__device__ float g_hTb[2][H * B];
__device__ float g_hTd[2][H * B];
__device__ float g_ghd[G3 * B];              // [j][b]
__device__ float g_Ah[B * H];                // [b][k]
__device__ float g_escore[B * S];
__device__ float g_cT[2 * H * B];            // packed float4 [k4][b]
__device__ float g_decout[B * T * H];
__device__ float g_logits[(size_t)B * T * V];
__device__ float g_rowres[B * T];

// grid barrier state
__device__ volatile unsigned g_gen;
__device__ unsigned g_cnt;

__device__ __forceinline__ float sigm(float x) { return 1.0f / (1.0f + expf(-x)); }
__device__ __forceinline__ float tanh_fast(float x) {
    float y; asm("tanh.approx.f32 %0, %1;" : "=f"(y) : "f"(x)); return y;
}

__device__ __forceinline__ void grid_sync(unsigned nb) {
    __syncthreads();
    if (threadIdx.x == 0) {
        unsigned gen = g_gen;
        __threadfence();
        if (atomicAdd(&g_cnt, 1u) == nb - 1) {
            g_cnt = 0;
            __threadfence();
            g_gen = gen + 1;
        } else {
            while (g_gen == gen) { }
        }
        __threadfence();
    }
    __syncthreads();
}

// ---------------- init ----------------
__global__ void zero_h_kernel() {
    int idx = blockIdx.x * blockDim.x + threadIdx.x;
    if (idx < H * B) {
        g_hTf[0][idx] = 0.f; g_hTb[0][idx] = 0.f; g_hTd[0][idx] = 0.f;
    }
    if (idx == 0) { g_cnt = 0; g_gen = 0; }
}

// ---------------- embedding gather ----------------
__global__ __launch_bounds__(128) void embed_kernel(
    const int* __restrict__ src_seqs, const int* __restrict__ tgt_seqs,
    const float* __restrict__ src_emb, const float* __restrict__ tgt_emb)
{
    int blk = blockIdx.x;
    int tid = threadIdx.x;
    if (blk < B * S) {
        int tok = src_seqs[blk];
        const float4* s = (const float4*)(src_emb + (size_t)tok * E);
        float4* d = (float4*)(g_esrc + (size_t)blk * E);
        d[tid] = s[tid];
    } else {
        int r = blk - B * S;
        int tok = tgt_seqs[r];
        const float4* s = (const float4*)(tgt_emb + (size_t)tok * E);
        float4* d = (float4*)(g_etgt + (size_t)r * E);
        d[tid] = s[tid];
    }
}

// ---------------- generic fp32 GEMM: C[M,N] = A[M,K] @ W[N,K]^T + bias ----------------
#define GBM 128
#define GBN 64
#define GBK 16
__global__ __launch_bounds__(256) void gemm_nt(
    const float* __restrict__ A, int lda,
    const float* __restrict__ W, int ldw,
    const float* __restrict__ bias,
    float* __restrict__ C, int ldc, int K)
{
    __shared__ float As[GBK][GBM];
    __shared__ float Bs[GBK][GBN];
    int tid = threadIdx.x;
    int m0 = blockIdx.y * GBM;
    int n0 = blockIdx.x * GBN;
    int tx = tid & 15, ty = tid >> 4;

    float acc[8][4];
#pragma unroll
    for (int i = 0; i < 8; i++)
#pragma unroll
        for (int j = 0; j < 4; j++) acc[i][j] = 0.f;

    int ar0 = tid >> 2;
    int ak0 = (tid & 3) * 4;
    int bn = tid >> 2;
    int bk0 = (tid & 3) * 4;

    for (int k0 = 0; k0 < K; k0 += GBK) {
#pragma unroll
        for (int h = 0; h < 2; h++) {
            int r = ar0 + h * 64;
            float4 v = *(const float4*)(A + (size_t)(m0 + r) * lda + k0 + ak0);
            As[ak0 + 0][r] = v.x; As[ak0 + 1][r] = v.y;
            As[ak0 + 2][r] = v.z; As[ak0 + 3][r] = v.w;
        }
        {
            float4 v = *(const float4*)(W + (size_t)(n0 + bn) * ldw + k0 + bk0);
            Bs[bk0 + 0][bn] = v.x; Bs[bk0 + 1][bn] = v.y;
            Bs[bk0 + 2][bn] = v.z; Bs[bk0 + 3][bn] = v.w;
        }
        __syncthreads();
#pragma unroll
        for (int kk = 0; kk < GBK; kk++) {
            float a[8], b[4];
#pragma unroll
            for (int i = 0; i < 8; i++) a[i] = As[kk][ty * 8 + i];
#pragma unroll
            for (int j = 0; j < 4; j++) b[j] = Bs[kk][tx * 4 + j];
#pragma unroll
            for (int i = 0; i < 8; i++)
#pragma unroll
                for (int j = 0; j < 4; j++) acc[i][j] = fmaf(a[i], b[j], acc[i][j]);
        }
        __syncthreads();
    }
    float b4[4];
#pragma unroll
    for (int j = 0; j < 4; j++) b4[j] = bias[n0 + tx * 4 + j];
#pragma unroll
    for (int i = 0; i < 8; i++) {
        int m = m0 + ty * 8 + i;
        float4 o;
        o.x = acc[i][0] + b4[0]; o.y = acc[i][1] + b4[1];
        o.z = acc[i][2] + b4[2]; o.w = acc[i][3] + b4[3];
        *(float4*)(C + (size_t)m * ldc + n0 + tx * 4) = o;
    }
}

// ---------------- persistent encoder: all S steps, grid-sync between ----------------
__global__ __launch_bounds__(128) void enc_persist(
    const float* __restrict__ Whh_f, const float* __restrict__ bhh_f,
    const float* __restrict__ Whh_b, const float* __restrict__ bhh_b,
    const int* __restrict__ src_lengths)
{
    int lane = threadIdx.x & 31;           // = b
    int w = threadIdx.x >> 5;
    int bx = blockIdx.x;
    int dir = bx >> 6;
    int j0 = (bx & 63) * 8 + w * 2;        // thread handles j0, j0+1
    const float* gx = dir ? g_gxb : g_gxf;
    const float* Whh = dir ? Whh_b : Whh_f;
    const float* bhh = dir ? bhh_b : bhh_f;
    float* hbuf0 = dir ? g_hTb[0] : g_hTf[0];
    float* hbuf1 = dir ? g_hTb[1] : g_hTf[1];
    int len = src_lengths[lane];

    const float* wr = Whh + (size_t)j0 * H;
    const float* wz = Whh + (size_t)(H + j0) * H;
    const float* wn = Whh + (size_t)(2 * H + j0) * H;
    float br0 = bhh[j0],     bz0 = bhh[H + j0],     bn0 = bhh[2 * H + j0];
    float br1 = bhh[j0 + 1], bz1 = bhh[H + j0 + 1], bn1 = bhh[2 * H + j0 + 1];

    for (int i = 0; i < S; i++) {
        int t = dir ? (S - 1 - i) : i;
        const float* hin = (i & 1) ? hbuf1 : hbuf0;
        float* hout = (i & 1) ? hbuf0 : hbuf1;

        float ar0 = br0, az0 = bz0, an0 = bn0;
        float ar1 = br1, az1 = bz1, an1 = bn1;
#pragma unroll 2
        for (int k4 = 0; k4 < H / 4; k4++) {
            float4 h4 = *(const float4*)(hin + (k4 * B + lane) * 4);
            int k = k4 * 4;
            float4 r0 = *(const float4*)(wr + k);
            float4 r1 = *(const float4*)(wr + H + k);
            float4 z0 = *(const float4*)(wz + k);
            float4 z1 = *(const float4*)(wz + H + k);
            float4 n0 = *(const float4*)(wn + k);
            float4 n1 = *(const float4*)(wn + H + k);
            ar0 = fmaf(r0.x, h4.x, ar0); ar0 = fmaf(r0.y, h4.y, ar0); ar0 = fmaf(r0.z, h4.z, ar0); ar0 = fmaf(r0.w, h4.w, ar0);
            ar1 = fmaf(r1.x, h4.x, ar1); ar1 = fmaf(r1.y, h4.y, ar1); ar1 = fmaf(r1.z, h4.z, ar1); ar1 = fmaf(r1.w, h4.w, ar1);
            az0 = fmaf(z0.x, h4.x, az0); az0 = fmaf(z0.y, h4.y, az0); az0 = fmaf(z0.z, h4.z, az0); az0 = fmaf(z0.w, h4.w, az0);
            az1 = fmaf(z1.x, h4.x, az1); az1 = fmaf(z1.y, h4.y, az1); az1 = fmaf(z1.z, h4.z, az1); az1 = fmaf(z1.w, h4.w, az1);
            an0 = fmaf(n0.x, h4.x, an0); an0 = fmaf(n0.y, h4.y, an0); an0 = fmaf(n0.z, h4.z, an0); an0 = fmaf(n0.w, h4.w, an0);
            an1 = fmaf(n1.x, h4.x, an1); an1 = fmaf(n1.y, h4.y, an1); an1 = fmaf(n1.z, h4.z, an1); an1 = fmaf(n1.w, h4.w, an1);
        }

        int base = (lane * S + t) * G3;
        int mask = t < len;
#pragma unroll
        for (int jj = 0; jj < 2; jj++) {
            int j = j0 + jj;
            float ar = jj ? ar1 : ar0, az = jj ? az1 : az0, an = jj ? an1 : an0;
            float r = sigm(gx[base + j] + ar);
            float z = sigm(gx[base + H + j] + az);
            float n = tanhf(gx[base + 2 * H + j] + r * an);
            int hidx = (j >> 2) * (B * 4) + lane * 4 + (j & 3);
            float hprev = hin[hidx];
            float hnew = (1.f - z) * n + z * hprev;
            hout[hidx] = mask ? hnew : hprev;
            g_srchid[(size_t)(lane * S + t) * (2 * H) + dir * H + j] = mask ? hnew : 0.f;
        }
        if (i < S - 1) grid_sync(ENC_BLOCKS);
    }
}

// ---------------- persistent decoder: all T steps, 4 phases each ----------------
__global__ __launch_bounds__(128) void dec_persist(
    const float* __restrict__ dec_Whh, const float* __restrict__ dec_bhh,
    const float* __restrict__ A_W, const float* __restrict__ A_b,
    const float* __restrict__ A_v, const float* __restrict__ dec_Wih,
    const int* __restrict__ src_lengths, const int* __restrict__ tgt_lengths)
{
    __shared__ float s_alpha[S];
    int tid = threadIdx.x;
    int lane = tid & 31;
    int w = tid >> 5;
    int bx = blockIdx.x;

    // ---- phase-1 mapping: 4 j per thread ----
    int j0 = bx * 16 + w * 4;
    bool is_att = (j0 >= G3);
    const float* wp[4];
    float bias1[4];
#pragma unroll
    for (int jj = 0; jj < 4; jj++) {
        int j = j0 + jj;
        if (!is_att) { wp[jj] = dec_Whh + (size_t)j * H; bias1[jj] = dec_bhh[j]; }
        else { int ja = j - G3; wp[jj] = A_W + (size_t)ja * H; bias1[jj] = A_b[ja]; }
    }

    // ---- phase-2 mapping ----
    int b2 = bx & 31, q2 = bx >> 5;
    int len2 = src_lengths[b2];
    float av[16];
#pragma unroll
    for (int m = 0; m < 16; m++) av[m] = A_v[lane + m * 32];

    // ---- phase-3 mapping: 1 j per thread (warp) ----
    int jh = bx * 4 + w;
    const float* w3r = dec_Wih + (size_t)jh * G3 + 512;
    const float* w3z = dec_Wih + (size_t)(512 + jh) * G3 + 512;
    const float* w3n = dec_Wih + (size_t)(1024 + jh) * G3 + 512;
    int mylen = tgt_lengths[lane];

    for (int i = 0; i < T; i++) {
        // ======== phase 1: gh = h@Whh^T + bhh ; Ah = h@A_W^T + A_b ========
        {
            const float* hin = g_hTd[i & 1];
            float acc[4] = {bias1[0], bias1[1], bias1[2], bias1[3]};
#pragma unroll 2
            for (int k4 = 0; k4 < H / 4; k4++) {
                float4 h4 = *(const float4*)(hin + (k4 * B + lane) * 4);
                int k = k4 * 4;
#pragma unroll
                for (int jj = 0; jj < 4; jj++) {
                    float4 wv = *(const float4*)(wp[jj] + k);
                    acc[jj] = fmaf(wv.x, h4.x, acc[jj]);
                    acc[jj] = fmaf(wv.y, h4.y, acc[jj]);
                    acc[jj] = fmaf(wv.z, h4.z, acc[jj]);
                    acc[jj] = fmaf(wv.w, h4.w, acc[jj]);
                }
            }
#pragma unroll
            for (int jj = 0; jj < 4; jj++) {
                int j = j0 + jj;
                if (!is_att) g_ghd[j * B + lane] = acc[jj];
                else g_Ah[lane * H + (j - G3)] = acc[jj];
            }
        }
        grid_sync(DEC_BLOCKS);

        // ======== phase 2a: attention scores ========
        {
            float ah[16];
#pragma unroll
            for (int m = 0; m < 16; m++) ah[m] = g_Ah[b2 * H + lane + m * 32];
#pragma unroll
            for (int si = 0; si < 4; si++) {
                int s = q2 * 16 + w * 4 + si;
                const float* uh = g_Uh + (size_t)(b2 * S + s) * H;
                float p = 0.f;
#pragma unroll
                for (int m = 0; m < 16; m++)
                    p = fmaf(av[m], tanh_fast(uh[lane + m * 32] + ah[m]), p);
#pragma unroll
                for (int off = 16; off; off >>= 1) p += __shfl_xor_sync(0xffffffffu, p, off);
                if (lane == 0) g_escore[b2 * S + s] = (s < len2) ? p : -1e9f;
            }
        }
        grid_sync(DEC_BLOCKS);

        // ======== phase 2b: softmax (replicated per CTA) + context ========
        {
            if (w == 0) {
                float e0 = g_escore[b2 * S + lane];
                float e1 = g_escore[b2 * S + lane + 32];
                float m = fmaxf(e0, e1);
#pragma unroll
                for (int off = 16; off; off >>= 1) m = fmaxf(m, __shfl_xor_sync(0xffffffffu, m, off));
                float x0 = __expf(e0 - m), x1 = __expf(e1 - m);
                float sm = x0 + x1;
#pragma unroll
                for (int off = 16; off; off >>= 1) sm += __shfl_xor_sync(0xffffffffu, sm, off);
                float inv = 1.0f / sm;
                s_alpha[lane] = x0 * inv;
                s_alpha[lane + 32] = x1 * inv;
            }
            __syncthreads();
            int k2 = q2 * 256 + tid * 2;
            const float* sh = g_srchid + (size_t)(b2 * S) * (2 * H) + k2;
            float a0 = 0.f, a1 = 0.f;
#pragma unroll 8
            for (int s = 0; s < S; s++) {
                float2 v = *(const float2*)(sh + (size_t)s * (2 * H));
                float al = s_alpha[s];
                a0 = fmaf(al, v.x, a0);
                a1 = fmaf(al, v.y, a1);
            }
            int cidx = (k2 >> 2) * (B * 4) + b2 * 4 + (k2 & 3);
            g_cT[cidx] = a0;
            g_cT[cidx + 1] = a1;   // k2+1 has same k4, next component
        }
        grid_sync(DEC_BLOCKS);

        // ======== phase 3: gx_c = c@Wih_c^T, gates, h update ========
        {
            float ar = 0.f, az = 0.f, an = 0.f;
#pragma unroll 2
            for (int k4 = 0; k4 < (2 * H) / 4; k4++) {
                float4 c4 = *(const float4*)(g_cT + (k4 * B + lane) * 4);
                int k = k4 * 4;
                float4 r4 = *(const float4*)(w3r + k);
                float4 z4 = *(const float4*)(w3z + k);
                float4 n4 = *(const float4*)(w3n + k);
                ar = fmaf(r4.x, c4.x, ar); ar = fmaf(r4.y, c4.y, ar); ar = fmaf(r4.z, c4.z, ar); ar = fmaf(r4.w, c4.w, ar);
                az = fmaf(z4.x, c4.x, az); az = fmaf(z4.y, c4.y, az); az = fmaf(z4.z, c4.z, az); az = fmaf(z4.w, c4.w, az);
                an = fmaf(n4.x, c4.x, an); an = fmaf(n4.y, c4.y, an); an = fmaf(n4.z, c4.z, an); an = fmaf(n4.w, c4.w, an);
            }
            int base = (lane * T + i) * G3;
            float gxr = g_gxemb[base + jh] + ar;
            float gxz = g_gxemb[base + 512 + jh] + az;
            float gxn = g_gxemb[base + 1024 + jh] + an;
            float ghr = g_ghd[jh * B + lane];
            float ghz = g_ghd[(512 + jh) * B + lane];
            float ghn = g_ghd[(1024 + jh) * B + lane];
            float r = sigm(gxr + ghr);
            float z = sigm(gxz + ghz);
            float n = tanhf(gxn + r * ghn);
            int hidx = (jh >> 2) * (B * 4) + lane * 4 + (jh & 3);
            float hprev = g_hTd[i & 1][hidx];
            float hnew = (1.f - z) * n + z * hprev;
            int mask = i < mylen;
            g_hTd[(i + 1) & 1][hidx] = mask ? hnew : hprev;
            g_decout[(size_t)(lane * T + i) * H + jh] = mask ? hnew : 0.f;
        }
        if (i < T - 1) grid_sync(DEC_BLOCKS);
    }
}

// ---------------- per-row logsumexp + picked logprob ----------------
__global__ __launch_bounds__(256) void row_lse(const int* __restrict__ tgt_seqs)
{
    int row = blockIdx.x;
    int b = row / T, t = row % T;
    const float* lg = g_logits + (size_t)row * V;
    __shared__ float sred[256];
    int tid = threadIdx.x;

    float m = -1e30f;
    for (int v = tid; v < V; v += 256) m = fmaxf(m, lg[v]);
    sred[tid] = m; __syncthreads();
    for (int s2 = 128; s2; s2 >>= 1) {
        if (tid < s2) sred[tid] = fmaxf(sred[tid], sred[tid + s2]);
        __syncthreads();
    }
    m = sred[0]; __syncthreads();

    float ss = 0.f;
    for (int v = tid; v < V; v += 256) ss += expf(lg[v] - m);
    sred[tid] = ss; __syncthreads();
    for (int s2 = 128; s2; s2 >>= 1) {
        if (tid < s2) sred[tid] += sred[tid + s2];
        __syncthreads();
    }
    if (tid == 0) {
        int goal = (t < T - 1) ? tgt_seqs[b * T + t + 1] : 0;
        float lse = m + logf(sred[0]);
        g_rowres[row] = (goal != 0) ? (lg[goal] - lse) : 0.f;
    }
}

// ---------------- final deterministic reduction ----------------
__global__ __launch_bounds__(256) void final_loss(
    const int* __restrict__ tgt_seqs, float* __restrict__ out)
{
    __shared__ float sp[256];
    __shared__ float sc[256];
    int tid = threadIdx.x;
    float ps = 0.f, pc = 0.f;
    for (int r = tid; r < B * T; r += 256) {
        ps += g_rowres[r];
        int b = r / T, t = r % T;
        int goal = (t < T - 1) ? tgt_seqs[b * T + t + 1] : 0;
        pc += (goal != 0) ? 1.f : 0.f;
    }
    sp[tid] = ps; sc[tid] = pc; __syncthreads();
    for (int s2 = 128; s2; s2 >>= 1) {
        if (tid < s2) { sp[tid] += sp[tid + s2]; sc[tid] += sc[tid + s2]; }
        __syncthreads();
    }
    if (tid == 0) out[0] = -sp[0] / sc[0];
}

// ---------------- host ----------------
extern "C" void kernel_launch(void* const* d_in, const int* in_sizes, int n_in,
                              void* d_out, int out_size)
{
    const int* src_seqs    = (const int*)d_in[0];
    const int* src_lengths = (const int*)d_in[1];
    const int* tgt_seqs    = (const int*)d_in[2];
    const int* tgt_lengths = (const int*)d_in[3];
    const float* src_emb   = (const float*)d_in[4];
    const float* enc_Wih_f = (const float*)d_in[5];
    const float* enc_Whh_f = (const float*)d_in[6];
    const float* enc_bih_f = (const float*)d_in[7];
    const float* enc_bhh_f = (const float*)d_in[8];
    const float* enc_Wih_b = (const float*)d_in[9];
    const float* enc_Whh_b = (const float*)d_in[10];
    const float* enc_bih_b = (const float*)d_in[11];
    const float* enc_bhh_b = (const float*)d_in[12];
    const float* tgt_emb   = (const float*)d_in[13];
    const float* dec_Wih   = (const float*)d_in[14];
    const float* dec_Whh   = (const float*)d_in[15];
    const float* dec_bih   = (const float*)d_in[16];
    const float* dec_bhh   = (const float*)d_in[17];
    const float* U_w       = (const float*)d_in[18];
    const float* U_b       = (const float*)d_in[19];
    const float* A_W       = (const float*)d_in[20];
    const float* A_b       = (const float*)d_in[21];
    const float* A_v       = (const float*)d_in[22];
    const float* out_w     = (const float*)d_in[23];
    const float* out_b     = (const float*)d_in[24];

    void *p_esrc, *p_etgt, *p_gxf, *p_gxb, *p_gxemb, *p_srchid, *p_Uh, *p_decout, *p_logits;
    cudaGetSymbolAddress(&p_esrc, g_esrc);
    cudaGetSymbolAddress(&p_etgt, g_etgt);
    cudaGetSymbolAddress(&p_gxf, g_gxf);
    cudaGetSymbolAddress(&p_gxb, g_gxb);
    cudaGetSymbolAddress(&p_gxemb, g_gxemb);
    cudaGetSymbolAddress(&p_srchid, g_srchid);
    cudaGetSymbolAddress(&p_Uh, g_Uh);
    cudaGetSymbolAddress(&p_decout, g_decout);
    cudaGetSymbolAddress(&p_logits, g_logits);

    zero_h_kernel<<<(H * B + 255) / 256, 256>>>();
    embed_kernel<<<B * S + B * T, 128>>>(src_seqs, tgt_seqs, src_emb, tgt_emb);

    // gx precompute GEMMs
    gemm_nt<<<dim3(G3 / GBN, (B * S) / GBM), 256>>>(
        (const float*)p_esrc, E, enc_Wih_f, E, enc_bih_f, (float*)p_gxf, G3, E);
    gemm_nt<<<dim3(G3 / GBN, (B * S) / GBM), 256>>>(
        (const float*)p_esrc, E, enc_Wih_b, E, enc_bih_b, (float*)p_gxb, G3, E);
    gemm_nt<<<dim3(G3 / GBN, (B * T) / GBM), 256>>>(
        (const float*)p_etgt, E, dec_Wih, G3, dec_bih, (float*)p_gxemb, G3, E);

    // persistent encoder (all S steps in one launch)
    enc_persist<<<ENC_BLOCKS, 128>>>(enc_Whh_f, enc_bhh_f, enc_Whh_b, enc_bhh_b, src_lengths);

    // Uh = src_hidden @ U_w^T + U_b
    gemm_nt<<<dim3(H / GBN, (B * S) / GBM), 256>>>(
        (const float*)p_srchid, 2 * H, U_w, 2 * H, U_b, (float*)p_Uh, H, 2 * H);

    // persistent decoder (all T steps in one launch)
    dec_persist<<<DEC_BLOCKS, 128>>>(dec_Whh, dec_bhh, A_W, A_b, A_v, dec_Wih,
                                     src_lengths, tgt_lengths);

    // logits = dec_out @ out_w^T + out_b
    gemm_nt<<<dim3(V / GBN, (B * T) / GBM), 256>>>(
        (const float*)p_decout, H, out_w, H, out_b, (float*)p_logits, V, H);

    row_lse<<<B * T, 256>>>(tgt_seqs);
    final_loss<<<1, 256>>>(tgt_seqs, (float*)d_out);
}